// round 15
// baseline (speedup 1.0000x reference)
#include <cuda_runtime.h>
#include <math.h>

#define BB 32
#define LL 1024
#define BLT (BB*LL)
#define DIN 63
#define DM 256
#define NCLS 14
#define NLAYER 4
#define DI 512
#define DS 128
#define NHH 8
#define HPP 64
#define DCV 4
#define CCH 768
#define PRJ 1288
#define EPSF 1e-5f

// ---------------- scratch (device globals; no cudaMalloc allowed) ----------
__device__ float g_h[BLT*DM];                 // residual (k-permuted cols)
__device__ float g_zx[(size_t)BLT*PRJ];       // inproj output (logical cols)
__device__ float g_xbc[(size_t)BLT*CCH];      // conv+silu output
__device__ float2 g_sc[BLT*NHH];              // packed (dA, dt)
__device__ float g_y[(size_t)BLT*DI];         // scan out (UNGATED) -> rms
__device__ float g_m[BLT*DM];                 // outproj output (logical cols)
__device__ float g_poolp[8][BB*DM];           // partial pools (permuted cols)
__device__ float g_win[(size_t)NLAYER*PRJ*DM];
__device__ float g_wout[(size_t)NLAYER*DM*DI];

// ---------------- column permutation: kp within 32-groups -------------------
__device__ __forceinline__ int permc(int j) {
    return (j & ~31) | (((j & 3) << 3) | ((j & 31) >> 2));
}
__device__ __forceinline__ int permcinv(int j) {
    return (j & ~31) | (((j & 7) << 2) | ((j & 31) >> 3));
}

__device__ __forceinline__ float to_tf32(float x) {
    asm("cvt.rna.tf32.f32 %0, %0;" : "+f"(x));
    return x;
}

// ---------------- fast silu: sigmoid via tanh.approx (1 MUFU) --------------
__device__ __forceinline__ float tanh_ap(float x) {
    float r;
    asm("tanh.approx.f32 %0, %1;" : "=f"(r) : "f"(x));
    return r;
}
__device__ __forceinline__ float silu_f(float x) {
    return x * fmaf(0.5f, tanh_ap(0.5f * x), 0.5f);
}

// ---------------- packed f32x2 helpers --------------------------------------
__device__ __forceinline__ unsigned long long pk2(float lo, float hi) {
    unsigned long long r;
    asm("mov.b64 %0, {%1, %2};" : "=l"(r) : "f"(lo), "f"(hi));
    return r;
}
__device__ __forceinline__ void upk2(float& lo, float& hi, unsigned long long v) {
    asm("mov.b64 {%0, %1}, %2;" : "=f"(lo), "=f"(hi) : "l"(v));
}
__device__ __forceinline__ unsigned long long mul2(unsigned long long a, unsigned long long b) {
    unsigned long long r;
    asm("mul.rn.f32x2 %0, %1, %2;" : "=l"(r) : "l"(a), "l"(b));
    return r;
}
__device__ __forceinline__ unsigned long long fma2(unsigned long long a, unsigned long long b,
                                                   unsigned long long c) {
    unsigned long long r;
    asm("fma.rn.f32x2 %0, %1, %2, %3;" : "=l"(r) : "l"(a), "l"(b), "l"(c));
    return r;
}

// ---------------- cp.async helper -------------------------------------------
__device__ __forceinline__ void cp16(void* dst, const void* src, bool v) {
    unsigned d = (unsigned)__cvta_generic_to_shared(dst);
    int sz = v ? 16 : 0;
    asm volatile("cp.async.ca.shared.global [%0], [%1], 16, %2;"
                 :: "r"(d), "l"(src), "r"(sz) : "memory");
}

// ---------------- weight permute + tf32 round pre-pass ----------------------
__global__ __launch_bounds__(256) void k_permw(const float* __restrict__ W,
                                               float* __restrict__ Wp,
                                               int total, int Kmask) {
    int i = blockIdx.x * 256 + threadIdx.x;
    if (i >= total) return;
    int k = i & Kmask;
    Wp[(i - k) + permc(k)] = to_tf32(W[i]);
}

// ---------------- block layernorm helper (blockDim == 256) -----------------
__device__ __forceinline__ void ln_write256(float acc, float* outp,
                                            const float* __restrict__ w,
                                            const float* __restrict__ b, int j) {
    __shared__ float s1[8], s2[8];
    float v = acc, v2 = acc * acc;
    int lane = j & 31, wp = j >> 5;
#pragma unroll
    for (int o = 16; o > 0; o >>= 1) {
        v  += __shfl_down_sync(0xffffffffu, v,  o);
        v2 += __shfl_down_sync(0xffffffffu, v2, o);
    }
    if (lane == 0) { s1[wp] = v; s2[wp] = v2; }
    __syncthreads();
    if (j == 0) {
        float a = 0.f, c = 0.f;
#pragma unroll
        for (int i = 0; i < 8; i++) { a += s1[i]; c += s2[i]; }
        s1[0] = a * (1.f / DM);
        s2[0] = c * (1.f / DM);
    }
    __syncthreads();
    float mu = s1[0], var = s2[0] - mu * mu;
    outp[permc(j)] = (acc - mu) * rsqrtf(var + EPSF) * w[j] + b[j];
}

// ---------------- input projection + layernorm ------------------------------
__global__ __launch_bounds__(256) void k_in_ln(const float* __restrict__ x,
                                               const float* __restrict__ w,
                                               const float* __restrict__ bias,
                                               const float* __restrict__ gw,
                                               const float* __restrict__ gb) {
    int row = blockIdx.x, j = threadIdx.x;
    __shared__ float sx[DIN];
    if (j < DIN) sx[j] = x[(size_t)row * DIN + j];
    __syncthreads();
    const float* wr = w + j * DIN;
    float acc = bias[j];
#pragma unroll
    for (int k = 0; k < DIN; k++) acc += sx[k] * wr[k];
    ln_write256(acc, g_h + (size_t)row * DM, gw, gb, j);
}

// ================= tf32 tensor-core GEMM (R4 proven version) ===============
__device__ __forceinline__ void mma8(float* c,
                                     unsigned a0, unsigned a1, unsigned a2, unsigned a3,
                                     unsigned b0, unsigned b1) {
    asm volatile(
        "mma.sync.aligned.m16n8k8.row.col.f32.tf32.tf32.f32 "
        "{%0,%1,%2,%3}, {%4,%5,%6,%7}, {%8,%9}, {%0,%1,%2,%3};"
        : "+f"(c[0]), "+f"(c[1]), "+f"(c[2]), "+f"(c[3])
        : "r"(a0), "r"(a1), "r"(a2), "r"(a3), "r"(b0), "r"(b1));
}

#define TPITCH 36
#define GEMM_SMEM (4 * 128 * TPITCH * 4)

template<bool CVTA>
__global__ __launch_bounds__(256, 2) void gemm_tf32(const float* __restrict__ A,
                                                    const float* __restrict__ B,
                                                    float* __restrict__ C,
                                                    int M, int N, int K) {
    extern __shared__ float smem_dyn[];
    float (*As)[128][TPITCH] = (float (*)[128][TPITCH])smem_dyn;
    float (*Bs)[128][TPITCH] = (float (*)[128][TPITCH])(smem_dyn + 2 * 128 * TPITCH);

    int tid = threadIdx.x;
    int bm = blockIdx.y * 128, bn = blockIdx.x * 128;
    int lane = tid & 31, warp = tid >> 5;
    int quad = lane >> 2, tq = lane & 3;
    int wm = (warp & 1) * 64, wn = (warp >> 1) * 32;
    int rr = tid >> 3, cc = tid & 7;

    float acc[4][4][4];
#pragma unroll
    for (int i = 0; i < 4; i++)
#pragma unroll
        for (int j = 0; j < 4; j++)
#pragma unroll
            for (int f = 0; f < 4; f++) acc[i][j][f] = 0.f;

#pragma unroll
    for (int i = 0; i < 4; i++) {
        int r = rr + i * 32;
        cp16(&Bs[0][r][cc * 4], B + (size_t)(bn + r) * K + cc * 4, bn + r < N);
        if (!CVTA)
            cp16(&As[0][r][cc * 4], A + (size_t)(bm + r) * K + cc * 4, true);
    }
    asm volatile("cp.async.commit_group;" ::: "memory");
    if (CVTA) {
#pragma unroll
        for (int i = 0; i < 4; i++) {
            float4 v = *(const float4*)(A + (size_t)(bm + rr + i * 32) * K + cc * 4);
            v.x = to_tf32(v.x); v.y = to_tf32(v.y);
            v.z = to_tf32(v.z); v.w = to_tf32(v.w);
            *(float4*)&As[0][rr + i * 32][cc * 4] = v;
        }
    }

    int nIter = K >> 5;
    for (int it = 0; it < nIter; it++) {
        int cur = it & 1, nb = cur ^ 1;
        bool more = (it + 1 < nIter);

        asm volatile("cp.async.wait_group 0;" ::: "memory");
        __syncthreads();

        if (more) {
            int k0 = (it + 1) << 5;
#pragma unroll
            for (int i = 0; i < 4; i++) {
                int r = rr + i * 32;
                cp16(&Bs[nb][r][cc * 4], B + (size_t)(bn + r) * K + k0 + cc * 4,
                     bn + r < N);
                if (!CVTA)
                    cp16(&As[nb][r][cc * 4], A + (size_t)(bm + r) * K + k0 + cc * 4,
                         true);
            }
            asm volatile("cp.async.commit_group;" ::: "memory");
        }

        __align__(16) unsigned bq[4][8];
#pragma unroll
        for (int j = 0; j < 4; j++) {
            const float* bp = &Bs[cur][wn + j * 8 + quad][tq * 8];
            *(float4*)&bq[j][0] = *(const float4*)bp;
            *(float4*)&bq[j][4] = *(const float4*)(bp + 4);
        }
#pragma unroll
        for (int i = 0; i < 4; i++) {
            __align__(16) unsigned alo[8], ahi[8];
            const float* ap0 = &As[cur][wm + i * 16 + quad][tq * 8];
            const float* ap1 = &As[cur][wm + i * 16 + 8 + quad][tq * 8];
            *(float4*)&alo[0] = *(const float4*)ap0;
            *(float4*)&alo[4] = *(const float4*)(ap0 + 4);
            *(float4*)&ahi[0] = *(const float4*)ap1;
            *(float4*)&ahi[4] = *(const float4*)(ap1 + 4);
#pragma unroll
            for (int j = 0; j < 4; j++)
#pragma unroll
                for (int s = 0; s < 4; s++)
                    mma8(acc[i][j], alo[2 * s], ahi[2 * s], alo[2 * s + 1],
                         ahi[2 * s + 1], bq[j][2 * s], bq[j][2 * s + 1]);
        }

        if (CVTA && more) {
            int k0 = (it + 1) << 5;
#pragma unroll
            for (int i = 0; i < 4; i++) {
                float4 v = *(const float4*)(A + (size_t)(bm + rr + i * 32) * K + k0 + cc * 4);
                v.x = to_tf32(v.x); v.y = to_tf32(v.y);
                v.z = to_tf32(v.z); v.w = to_tf32(v.w);
                *(float4*)&As[nb][rr + i * 32][cc * 4] = v;
            }
        }
    }

#pragma unroll
    for (int i = 0; i < 4; i++) {
        int row = bm + wm + i * 16 + quad;
#pragma unroll
        for (int j = 0; j < 4; j++) {
            int col = bn + wn + j * 8 + tq * 2;
            if (col < N) {
                float2 v0 = make_float2(acc[i][j][0], acc[i][j][1]);
                float2 v1 = make_float2(acc[i][j][2], acc[i][j][3]);
                *(float2*)(C + (size_t)row * N + col) = v0;
                *(float2*)(C + (size_t)(row + 8) * N + col) = v1;
            }
        }
    }
}

// ---------------- causal depthwise conv + silu (tanh-based, 1 MUFU) --------
__global__ __launch_bounds__(256) void k_conv(const float* __restrict__ cw,
                                              const float* __restrict__ cb) {
    int idx = blockIdx.x * 256 + threadIdx.x;
    int c = idx % CCH;
    int row = idx / CCH;
    int t = row & (LL - 1);
    const float* base = g_zx + (size_t)row * PRJ + DI + c;
    float acc = cb[c];
#pragma unroll
    for (int k = 0; k < DCV; k++) {
        int tt = t + k - (DCV - 1);
        if (tt >= 0) acc += base[(long)(k - (DCV - 1)) * PRJ] * cw[k * CCH + c];
    }
    g_xbc[(size_t)row * CCH + c] = silu_f(acc);
}

// ---------------- dt/dA: packed (dA, dt) float2 -----------------------------
__global__ __launch_bounds__(256) void k_dt(const float* __restrict__ dtb,
                                            const float* __restrict__ alog) {
    int idx = blockIdx.x * 256 + threadIdx.x;
    int row = idx >> 3, hh = idx & 7;
    float v = g_zx[(size_t)row * PRJ + DI + CCH + hh] + dtb[hh];
    float dt = (v > 20.f) ? v : log1pf(expf(v));
    float A = -expf(alog[hh]);
    g_sc[idx] = make_float2(expf(dt * A), dt);
}

// ---------------- sequential SSM scan: p-split x2, 8pg x 32ng ---------------
// grid (2, BB*NHH): blockIdx.x = p-half. 256 threads: ng = lane (32 groups of
// 4 n-floats -> B/C loads perfectly warp-coalesced, NO intra-warp replication),
// pg = warp (8 groups of 4 p). Per thread 4p x 4n states (8 ull). Depth-2
// register prefetch. Writes UNGATED y + D*x; k_rms applies silu(z).
// Total chip B/C traffic identical to R14 (blocks x pg constant), 2x warps.
#define SCAN_LOAD(S, T)                                               \
    do {                                                              \
        const float* r_ = xbase + (size_t)(T) * CCH;                  \
        b##S = *(const float4*)(r_ + OB);                             \
        c##S = *(const float4*)(r_ + OC);                             \
        x##S = *(const float4*)(r_ + OX);                             \
        s##S = scbase[(size_t)(T) * NHH];                             \
    } while (0)

#define SCAN_STEP(S, T)                                                     \
    do {                                                                    \
        unsigned long long dA2 = pk2(s##S.x, s##S.x);                       \
        float dtv = s##S.y;                                                 \
        float xa[4] = {x##S.x, x##S.y, x##S.z, x##S.w};                     \
        unsigned long long bp[2], cp[2], dtx2[4], accp[4];                  \
        bp[0] = pk2(b##S.x, b##S.y); bp[1] = pk2(b##S.z, b##S.w);           \
        cp[0] = pk2(c##S.x, c##S.y); cp[1] = pk2(c##S.z, c##S.w);           \
        if ((T) + 2 < LL) SCAN_LOAD(S, (T) + 2);                            \
        _Pragma("unroll")                                                   \
        for (int i = 0; i < 4; i++) {                                       \
            float d = dtv * xa[i];                                          \
            dtx2[i] = pk2(d, d);                                            \
            accp[i] = 0ull;                                                 \
        }                                                                   \
        _Pragma("unroll")                                                   \
        for (int i = 0; i < 4; i++)                                         \
            _Pragma("unroll")                                               \
            for (int j = 0; j < 2; j++) {                                   \
                hs[i][j] = fma2(dtx2[i], bp[j], mul2(hs[i][j], dA2));       \
                accp[i] = fma2(hs[i][j], cp[j], accp[i]);                   \
            }                                                               \
        float acc[4];                                                       \
        _Pragma("unroll")                                                   \
        for (int i = 0; i < 4; i++) {                                       \
            float lo, hi;                                                   \
            upk2(lo, hi, accp[i]);                                          \
            acc[i] = lo + hi;                                               \
        }                                                                   \
        _Pragma("unroll")                                                   \
        for (int o = 16; o > 0; o >>= 1)                                    \
            _Pragma("unroll")                                               \
            for (int i = 0; i < 4; i++)                                     \
                acc[i] += __shfl_down_sync(0xffffffffu, acc[i], o);         \
        if (ng == 0) {                                                      \
            float4 yo;                                                      \
            yo.x = acc[0] + Dh * xa[0];                                     \
            yo.y = acc[1] + Dh * xa[1];                                     \
            yo.z = acc[2] + Dh * xa[2];                                     \
            yo.w = acc[3] + Dh * xa[3];                                     \
            *(float4*)(ybase + (size_t)(T) * DI) = yo;                      \
        }                                                                   \
    } while (0)

__global__ __launch_bounds__(256, 2) void k_scan(const float* __restrict__ Dp) {
    int phalf = blockIdx.x;
    int bh = blockIdx.y, b = bh >> 3, hh = bh & 7;
    int tid = threadIdx.x;
    int pg = tid >> 5, ng = tid & 31;
    int p0 = phalf * 32 + pg * 4, n0 = ng * 4;

    unsigned long long hs[4][2];          // 4p x 4n packed
#pragma unroll
    for (int i = 0; i < 4; i++)
#pragma unroll
        for (int j = 0; j < 2; j++) hs[i][j] = 0ull;

    const float* xbase = g_xbc + (size_t)b * LL * CCH;
    const int OB = DI + n0;
    const int OC = DI + DS + n0;
    const int OX = hh * HPP + p0;
    const float2* scbase = g_sc + (size_t)b * LL * NHH + hh;
    float* ybase = g_y + (size_t)b * LL * DI + hh * HPP + p0;
    float Dh = Dp[hh];

    float4 bA, cA, xA;
    float4 bB, cB, xB;
    float2 sA, sB;

    SCAN_LOAD(A, 0);
    SCAN_LOAD(B, 1);

    for (int t = 0; t < LL; t += 2) {
        SCAN_STEP(A, t);
        SCAN_STEP(B, t + 1);
    }
}

// ---------------- RMS norm: fused silu(z) gate + rms + permute + tf32 ------
__global__ __launch_bounds__(256) void k_rms(const float* __restrict__ nw) {
    int row = blockIdx.x, j = threadIdx.x;
    size_t rD = (size_t)row * DI;
    const float* zr = g_zx + (size_t)row * PRJ;
    float a0 = g_y[rD + j]       * silu_f(zr[j]);
    float a1 = g_y[rD + 256 + j] * silu_f(zr[256 + j]);
    float v = a0 * a0 + a1 * a1;
    __shared__ float s1[8];
    int lane = j & 31, w = j >> 5;
#pragma unroll
    for (int o = 16; o > 0; o >>= 1) v += __shfl_down_sync(0xffffffffu, v, o);
    if (lane == 0) s1[w] = v;
    __syncthreads();
    if (j == 0) {
        float a = 0.f;
#pragma unroll
        for (int i = 0; i < 8; i++) a += s1[i];
        s1[0] = a * (1.f / DI);
    }
    __syncthreads();
    float sc = rsqrtf(s1[0] + EPSF);
    int pj = permc(j);
    g_y[rD + pj]       = to_tf32(a0 * sc * nw[j]);
    g_y[rD + 256 + pj] = to_tf32(a1 * sc * nw[j + 256]);
}

// ---------------- residual add + layernorm (g_h permuted in/out) ------------
__global__ __launch_bounds__(256) void k_addln(const float* __restrict__ lw,
                                               const float* __restrict__ lb) {
    int row = blockIdx.x, j = threadIdx.x;
    float acc = g_m[(size_t)row * DM + j] + g_h[(size_t)row * DM + permc(j)];
    ln_write256(acc, g_h + (size_t)row * DM, lw, lb, j);
}

// ---------------- masked mean pool (permuted cols, 8 t-slices) --------------
__global__ __launch_bounds__(256) void k_pool(const int* __restrict__ lengths) {
    int b = blockIdx.x, s = blockIdx.y, d = threadIdx.x;
    int len = lengths[b];
    int t0 = s * 128;
    int t1 = min(t0 + 128, len);
    float acc = 0.f;
    const float* base = g_h + ((size_t)b * LL + t0) * DM + d;
#pragma unroll 4
    for (int t = t0; t < t1; t++, base += DM) acc += *base;
    g_poolp[s][b * DM + d] = acc;
}

// ---------------- classification head ---------------------------------------
__global__ __launch_bounds__(NCLS*32) void k_head(const float* __restrict__ hw,
                                                  const float* __restrict__ hb,
                                                  const int* __restrict__ lengths,
                                                  float* __restrict__ out) {
    int b = blockIdx.x;
    int tid = threadIdx.x, c = tid >> 5, lane = tid & 31;
    __shared__ float sp[DM];
    if (tid < DM) {
        float a = 0.f;
#pragma unroll
        for (int s = 0; s < 8; s++) a += g_poolp[s][b * DM + tid];
        sp[permcinv(tid)] = a / (float)lengths[b];
    }
    __syncthreads();
    float acc = 0.f;
    for (int k = lane; k < DM; k += 32) acc += sp[k] * hw[c * DM + k];
#pragma unroll
    for (int o = 16; o > 0; o >>= 1) acc += __shfl_down_sync(0xffffffffu, acc, o);
    if (lane == 0) out[b * NCLS + c] = acc + hb[c];
}

// ---------------- launcher ---------------------------------------------------
extern "C" void kernel_launch(void* const* d_in, const int* in_sizes, int n_in,
                              void* d_out, int out_size) {
    (void)in_sizes; (void)n_in; (void)out_size;
    const float* x        = (const float*)d_in[0];
    const float* in_w     = (const float*)d_in[1];
    const float* in_b     = (const float*)d_in[2];
    const float* lnin_w   = (const float*)d_in[3];
    const float* lnin_b   = (const float*)d_in[4];
    const float* inproj_w = (const float*)d_in[5];
    const float* conv_w   = (const float*)d_in[6];
    const float* conv_b   = (const float*)d_in[7];
    const float* dt_bias  = (const float*)d_in[8];
    const float* A_log    = (const float*)d_in[9];
    const float* Dp       = (const float*)d_in[10];
    const float* norm_w   = (const float*)d_in[11];
    const float* outp_w   = (const float*)d_in[12];
    const float* ln_w     = (const float*)d_in[13];
    const float* ln_b     = (const float*)d_in[14];
    const float* head_w   = (const float*)d_in[15];
    const float* head_b   = (const float*)d_in[16];
    const int*   lengths  = (const int*)d_in[17];
    float* out = (float*)d_out;

    float *ph, *pzx, *py, *pm, *pwin, *pwout;
    cudaGetSymbolAddress((void**)&ph,    g_h);
    cudaGetSymbolAddress((void**)&pzx,   g_zx);
    cudaGetSymbolAddress((void**)&py,    g_y);
    cudaGetSymbolAddress((void**)&pm,    g_m);
    cudaGetSymbolAddress((void**)&pwin,  g_win);
    cudaGetSymbolAddress((void**)&pwout, g_wout);

    cudaFuncSetAttribute(gemm_tf32<true>,  cudaFuncAttributeMaxDynamicSharedMemorySize,
                         GEMM_SMEM);
    cudaFuncSetAttribute(gemm_tf32<false>, cudaFuncAttributeMaxDynamicSharedMemorySize,
                         GEMM_SMEM);

    int totIn  = NLAYER * PRJ * DM;
    int totOut = NLAYER * DM * DI;
    k_permw<<<(totIn  + 255) / 256, 256>>>(inproj_w, pwin,  totIn,  DM - 1);
    k_permw<<<(totOut + 255) / 256, 256>>>(outp_w,   pwout, totOut, DI - 1);

    k_in_ln<<<BLT, 256>>>(x, in_w, in_b, lnin_w, lnin_b);
    for (int i = 0; i < NLAYER; i++) {
        gemm_tf32<true><<<dim3((PRJ + 127) / 128, BLT / 128), 256, GEMM_SMEM>>>(
            ph, pwin + (size_t)i * PRJ * DM, pzx, BLT, PRJ, DM);
        k_conv<<<(BLT * CCH) / 256, 256>>>(conv_w + i * DCV * CCH, conv_b + i * CCH);
        k_dt<<<(BLT * NHH) / 256, 256>>>(dt_bias + i * NHH, A_log + i * NHH);
        k_scan<<<dim3(2, BB * NHH), 256>>>(Dp + i * NHH);
        k_rms<<<BLT, 256>>>(norm_w + i * DI);
        gemm_tf32<false><<<dim3(DM / 128, BLT / 128), 256, GEMM_SMEM>>>(
            py, pwout + (size_t)i * DM * DI, pm, BLT, DM, DI);
        k_addln<<<BLT, 256>>>(ln_w + i * DM, ln_b + i * DM);
    }
    k_pool<<<dim3(BB, 8), 256>>>(lengths);
    k_head<<<BB, NCLS * 32>>>(head_w, head_b, lengths, out);
}

// round 16
// speedup vs baseline: 1.2097x; 1.2097x over previous
#include <cuda_runtime.h>
#include <math.h>

#define BB 32
#define LL 1024
#define BLT (BB*LL)
#define DIN 63
#define DM 256
#define NCLS 14
#define NLAYER 4
#define DI 512
#define DS 128
#define NHH 8
#define HPP 64
#define DCV 4
#define CCH 768
#define PRJ 1288
#define EPSF 1e-5f

// ---------------- scratch (device globals; no cudaMalloc allowed) ----------
__device__ float g_h[BLT*DM];                 // residual (k-permuted cols)
__device__ float g_zx[(size_t)BLT*PRJ];       // inproj output (logical cols)
__device__ float g_xbc[(size_t)BLT*CCH];      // conv+silu output
__device__ float2 g_sc[BLT*NHH];              // packed (dA, dt)
__device__ float g_y[(size_t)BLT*DI];         // scan out (UNGATED) -> rms
__device__ float g_m[BLT*DM];                 // outproj output (logical cols)
__device__ float g_poolp[8][BB*DM];           // partial pools (permuted cols)
__device__ float g_win[(size_t)NLAYER*PRJ*DM];
__device__ float g_wout[(size_t)NLAYER*DM*DI];

// ---------------- column permutation: kp within 32-groups -------------------
__device__ __forceinline__ int permc(int j) {
    return (j & ~31) | (((j & 3) << 3) | ((j & 31) >> 2));
}
__device__ __forceinline__ int permcinv(int j) {
    return (j & ~31) | (((j & 7) << 2) | ((j & 31) >> 3));
}

__device__ __forceinline__ float to_tf32(float x) {
    asm("cvt.rna.tf32.f32 %0, %0;" : "+f"(x));
    return x;
}

// ---------------- fast silu: sigmoid via tanh.approx (1 MUFU) --------------
__device__ __forceinline__ float tanh_ap(float x) {
    float r;
    asm("tanh.approx.f32 %0, %1;" : "=f"(r) : "f"(x));
    return r;
}
__device__ __forceinline__ float silu_f(float x) {
    return x * fmaf(0.5f, tanh_ap(0.5f * x), 0.5f);
}

// ---------------- packed f32x2 helpers --------------------------------------
__device__ __forceinline__ unsigned long long pk2(float lo, float hi) {
    unsigned long long r;
    asm("mov.b64 %0, {%1, %2};" : "=l"(r) : "f"(lo), "f"(hi));
    return r;
}
__device__ __forceinline__ void upk2(float& lo, float& hi, unsigned long long v) {
    asm("mov.b64 {%0, %1}, %2;" : "=f"(lo), "=f"(hi) : "l"(v));
}
__device__ __forceinline__ unsigned long long mul2(unsigned long long a, unsigned long long b) {
    unsigned long long r;
    asm("mul.rn.f32x2 %0, %1, %2;" : "=l"(r) : "l"(a), "l"(b));
    return r;
}
__device__ __forceinline__ unsigned long long fma2(unsigned long long a, unsigned long long b,
                                                   unsigned long long c) {
    unsigned long long r;
    asm("fma.rn.f32x2 %0, %1, %2, %3;" : "=l"(r) : "l"(a), "l"(b), "l"(c));
    return r;
}

// ---------------- cp.async helper -------------------------------------------
__device__ __forceinline__ void cp16(void* dst, const void* src, bool v) {
    unsigned d = (unsigned)__cvta_generic_to_shared(dst);
    int sz = v ? 16 : 0;
    asm volatile("cp.async.ca.shared.global [%0], [%1], 16, %2;"
                 :: "r"(d), "l"(src), "r"(sz) : "memory");
}

// ---------------- weight permute + tf32 round pre-pass ----------------------
__global__ __launch_bounds__(256) void k_permw(const float* __restrict__ W,
                                               float* __restrict__ Wp,
                                               int total, int Kmask) {
    int i = blockIdx.x * 256 + threadIdx.x;
    if (i >= total) return;
    int k = i & Kmask;
    Wp[(i - k) + permc(k)] = to_tf32(W[i]);
}

// ---------------- block layernorm helper (blockDim == 256) -----------------
__device__ __forceinline__ void ln_write256(float acc, float* outp,
                                            const float* __restrict__ w,
                                            const float* __restrict__ b, int j) {
    __shared__ float s1[8], s2[8];
    float v = acc, v2 = acc * acc;
    int lane = j & 31, wp = j >> 5;
#pragma unroll
    for (int o = 16; o > 0; o >>= 1) {
        v  += __shfl_down_sync(0xffffffffu, v,  o);
        v2 += __shfl_down_sync(0xffffffffu, v2, o);
    }
    if (lane == 0) { s1[wp] = v; s2[wp] = v2; }
    __syncthreads();
    if (j == 0) {
        float a = 0.f, c = 0.f;
#pragma unroll
        for (int i = 0; i < 8; i++) { a += s1[i]; c += s2[i]; }
        s1[0] = a * (1.f / DM);
        s2[0] = c * (1.f / DM);
    }
    __syncthreads();
    float mu = s1[0], var = s2[0] - mu * mu;
    outp[permc(j)] = (acc - mu) * rsqrtf(var + EPSF) * w[j] + b[j];
}

// ---------------- input projection + layernorm ------------------------------
__global__ __launch_bounds__(256) void k_in_ln(const float* __restrict__ x,
                                               const float* __restrict__ w,
                                               const float* __restrict__ bias,
                                               const float* __restrict__ gw,
                                               const float* __restrict__ gb) {
    int row = blockIdx.x, j = threadIdx.x;
    __shared__ float sx[DIN];
    if (j < DIN) sx[j] = x[(size_t)row * DIN + j];
    __syncthreads();
    const float* wr = w + j * DIN;
    float acc = bias[j];
#pragma unroll
    for (int k = 0; k < DIN; k++) acc += sx[k] * wr[k];
    ln_write256(acc, g_h + (size_t)row * DM, gw, gb, j);
}

// ================= tf32 tensor-core GEMM (R4 proven version) ===============
__device__ __forceinline__ void mma8(float* c,
                                     unsigned a0, unsigned a1, unsigned a2, unsigned a3,
                                     unsigned b0, unsigned b1) {
    asm volatile(
        "mma.sync.aligned.m16n8k8.row.col.f32.tf32.tf32.f32 "
        "{%0,%1,%2,%3}, {%4,%5,%6,%7}, {%8,%9}, {%0,%1,%2,%3};"
        : "+f"(c[0]), "+f"(c[1]), "+f"(c[2]), "+f"(c[3])
        : "r"(a0), "r"(a1), "r"(a2), "r"(a3), "r"(b0), "r"(b1));
}

#define TPITCH 36
#define GEMM_SMEM (4 * 128 * TPITCH * 4)

template<bool CVTA>
__global__ __launch_bounds__(256, 2) void gemm_tf32(const float* __restrict__ A,
                                                    const float* __restrict__ B,
                                                    float* __restrict__ C,
                                                    int M, int N, int K) {
    extern __shared__ float smem_dyn[];
    float (*As)[128][TPITCH] = (float (*)[128][TPITCH])smem_dyn;
    float (*Bs)[128][TPITCH] = (float (*)[128][TPITCH])(smem_dyn + 2 * 128 * TPITCH);

    int tid = threadIdx.x;
    int bm = blockIdx.y * 128, bn = blockIdx.x * 128;
    int lane = tid & 31, warp = tid >> 5;
    int quad = lane >> 2, tq = lane & 3;
    int wm = (warp & 1) * 64, wn = (warp >> 1) * 32;
    int rr = tid >> 3, cc = tid & 7;

    float acc[4][4][4];
#pragma unroll
    for (int i = 0; i < 4; i++)
#pragma unroll
        for (int j = 0; j < 4; j++)
#pragma unroll
            for (int f = 0; f < 4; f++) acc[i][j][f] = 0.f;

#pragma unroll
    for (int i = 0; i < 4; i++) {
        int r = rr + i * 32;
        cp16(&Bs[0][r][cc * 4], B + (size_t)(bn + r) * K + cc * 4, bn + r < N);
        if (!CVTA)
            cp16(&As[0][r][cc * 4], A + (size_t)(bm + r) * K + cc * 4, true);
    }
    asm volatile("cp.async.commit_group;" ::: "memory");
    if (CVTA) {
#pragma unroll
        for (int i = 0; i < 4; i++) {
            float4 v = *(const float4*)(A + (size_t)(bm + rr + i * 32) * K + cc * 4);
            v.x = to_tf32(v.x); v.y = to_tf32(v.y);
            v.z = to_tf32(v.z); v.w = to_tf32(v.w);
            *(float4*)&As[0][rr + i * 32][cc * 4] = v;
        }
    }

    int nIter = K >> 5;
    for (int it = 0; it < nIter; it++) {
        int cur = it & 1, nb = cur ^ 1;
        bool more = (it + 1 < nIter);

        asm volatile("cp.async.wait_group 0;" ::: "memory");
        __syncthreads();

        if (more) {
            int k0 = (it + 1) << 5;
#pragma unroll
            for (int i = 0; i < 4; i++) {
                int r = rr + i * 32;
                cp16(&Bs[nb][r][cc * 4], B + (size_t)(bn + r) * K + k0 + cc * 4,
                     bn + r < N);
                if (!CVTA)
                    cp16(&As[nb][r][cc * 4], A + (size_t)(bm + r) * K + k0 + cc * 4,
                         true);
            }
            asm volatile("cp.async.commit_group;" ::: "memory");
        }

        __align__(16) unsigned bq[4][8];
#pragma unroll
        for (int j = 0; j < 4; j++) {
            const float* bp = &Bs[cur][wn + j * 8 + quad][tq * 8];
            *(float4*)&bq[j][0] = *(const float4*)bp;
            *(float4*)&bq[j][4] = *(const float4*)(bp + 4);
        }
#pragma unroll
        for (int i = 0; i < 4; i++) {
            __align__(16) unsigned alo[8], ahi[8];
            const float* ap0 = &As[cur][wm + i * 16 + quad][tq * 8];
            const float* ap1 = &As[cur][wm + i * 16 + 8 + quad][tq * 8];
            *(float4*)&alo[0] = *(const float4*)ap0;
            *(float4*)&alo[4] = *(const float4*)(ap0 + 4);
            *(float4*)&ahi[0] = *(const float4*)ap1;
            *(float4*)&ahi[4] = *(const float4*)(ap1 + 4);
#pragma unroll
            for (int j = 0; j < 4; j++)
#pragma unroll
                for (int s = 0; s < 4; s++)
                    mma8(acc[i][j], alo[2 * s], ahi[2 * s], alo[2 * s + 1],
                         ahi[2 * s + 1], bq[j][2 * s], bq[j][2 * s + 1]);
        }

        if (CVTA && more) {
            int k0 = (it + 1) << 5;
#pragma unroll
            for (int i = 0; i < 4; i++) {
                float4 v = *(const float4*)(A + (size_t)(bm + rr + i * 32) * K + k0 + cc * 4);
                v.x = to_tf32(v.x); v.y = to_tf32(v.y);
                v.z = to_tf32(v.z); v.w = to_tf32(v.w);
                *(float4*)&As[nb][rr + i * 32][cc * 4] = v;
            }
        }
    }

#pragma unroll
    for (int i = 0; i < 4; i++) {
        int row = bm + wm + i * 16 + quad;
#pragma unroll
        for (int j = 0; j < 4; j++) {
            int col = bn + wn + j * 8 + tq * 2;
            if (col < N) {
                float2 v0 = make_float2(acc[i][j][0], acc[i][j][1]);
                float2 v1 = make_float2(acc[i][j][2], acc[i][j][3]);
                *(float2*)(C + (size_t)row * N + col) = v0;
                *(float2*)(C + (size_t)(row + 8) * N + col) = v1;
            }
        }
    }
}

// ---------------- causal depthwise conv + silu (tanh-based, 1 MUFU) --------
__global__ __launch_bounds__(256) void k_conv(const float* __restrict__ cw,
                                              const float* __restrict__ cb) {
    int idx = blockIdx.x * 256 + threadIdx.x;
    int c = idx % CCH;
    int row = idx / CCH;
    int t = row & (LL - 1);
    const float* base = g_zx + (size_t)row * PRJ + DI + c;
    float acc = cb[c];
#pragma unroll
    for (int k = 0; k < DCV; k++) {
        int tt = t + k - (DCV - 1);
        if (tt >= 0) acc += base[(long)(k - (DCV - 1)) * PRJ] * cw[k * CCH + c];
    }
    g_xbc[(size_t)row * CCH + c] = silu_f(acc);
}

// ---------------- dt/dA: packed (dA, dt) float2 -----------------------------
__global__ __launch_bounds__(256) void k_dt(const float* __restrict__ dtb,
                                            const float* __restrict__ alog) {
    int idx = blockIdx.x * 256 + threadIdx.x;
    int row = idx >> 3, hh = idx & 7;
    float v = g_zx[(size_t)row * PRJ + DI + CCH + hh] + dtb[hh];
    float dt = (v > 20.f) ? v : log1pf(expf(v));
    float A = -expf(alog[hh]);
    g_sc[idx] = make_float2(expf(dt * A), dt);
}

// ---------------- sequential SSM scan: warp-transposed layout ---------------
// one block per (b,h); 256 threads = 8 warps. ng = lane (32 groups x 4n):
// B/C loads are 1 coalesced float4/lane (1 wavefront/warp, replication 8x/block
// instead of 16x). pg = warp (8 groups x 8p): x is 2 broadcast float4s.
// Per thread 8p x 4n states (16 ull). Depth-2 register prefetch. Writes
// UNGATED y + D*x (lane 0, 2 float4s); k_rms applies silu(z).
#define SCAN_LOAD(S, T)                                               \
    do {                                                              \
        const float* r_ = xbase + (size_t)(T) * CCH;                  \
        b##S  = *(const float4*)(r_ + OB);                            \
        c##S  = *(const float4*)(r_ + OC);                            \
        x0##S = *(const float4*)(r_ + OX);                            \
        x1##S = *(const float4*)(r_ + OX + 4);                        \
        s##S  = scbase[(size_t)(T) * NHH];                            \
    } while (0)

#define SCAN_STEP(S, T)                                                     \
    do {                                                                    \
        unsigned long long dA2 = pk2(s##S.x, s##S.x);                       \
        float dtv = s##S.y;                                                 \
        float xa[8] = {x0##S.x, x0##S.y, x0##S.z, x0##S.w,                  \
                       x1##S.x, x1##S.y, x1##S.z, x1##S.w};                 \
        unsigned long long bp[2], cq[2];                                    \
        bp[0] = pk2(b##S.x, b##S.y); bp[1] = pk2(b##S.z, b##S.w);           \
        cq[0] = pk2(c##S.x, c##S.y); cq[1] = pk2(c##S.z, c##S.w);           \
        if ((T) + 2 < LL) SCAN_LOAD(S, (T) + 2);                            \
        float acc[8];                                                       \
        _Pragma("unroll")                                                   \
        for (int i = 0; i < 8; i++) {                                       \
            float d = dtv * xa[i];                                          \
            unsigned long long dtx = pk2(d, d);                             \
            unsigned long long ap = 0ull;                                   \
            _Pragma("unroll")                                               \
            for (int j = 0; j < 2; j++) {                                   \
                hs[i][j] = fma2(dtx, bp[j], mul2(hs[i][j], dA2));           \
                ap = fma2(hs[i][j], cq[j], ap);                             \
            }                                                               \
            float lo, hi;                                                   \
            upk2(lo, hi, ap);                                               \
            acc[i] = lo + hi;                                               \
        }                                                                   \
        _Pragma("unroll")                                                   \
        for (int o = 16; o > 0; o >>= 1)                                    \
            _Pragma("unroll")                                               \
            for (int i = 0; i < 8; i++)                                     \
                acc[i] += __shfl_down_sync(0xffffffffu, acc[i], o);         \
        if (lane == 0) {                                                    \
            float4 y0, y1;                                                  \
            y0.x = acc[0] + Dh * xa[0]; y0.y = acc[1] + Dh * xa[1];         \
            y0.z = acc[2] + Dh * xa[2]; y0.w = acc[3] + Dh * xa[3];         \
            y1.x = acc[4] + Dh * xa[4]; y1.y = acc[5] + Dh * xa[5];         \
            y1.z = acc[6] + Dh * xa[6]; y1.w = acc[7] + Dh * xa[7];         \
            *(float4*)(ybase + (size_t)(T) * DI)     = y0;                  \
            *(float4*)(ybase + (size_t)(T) * DI + 4) = y1;                  \
        }                                                                   \
    } while (0)

__global__ __launch_bounds__(256, 2) void k_scan(const float* __restrict__ Dp) {
    int bh = blockIdx.x, b = bh >> 3, hh = bh & 7;
    int tid = threadIdx.x;
    int warp = tid >> 5, lane = tid & 31;
    int p0 = warp * 8, n0 = lane * 4;

    unsigned long long hs[8][2];          // 8p x 4n packed
#pragma unroll
    for (int i = 0; i < 8; i++)
#pragma unroll
        for (int j = 0; j < 2; j++) hs[i][j] = 0ull;

    const float* xbase = g_xbc + (size_t)b * LL * CCH;
    const int OB = DI + n0;
    const int OC = DI + DS + n0;
    const int OX = hh * HPP + p0;
    const float2* scbase = g_sc + (size_t)b * LL * NHH + hh;
    float* ybase = g_y + (size_t)b * LL * DI + hh * HPP + p0;
    float Dh = Dp[hh];

    float4 bA, cA, x0A, x1A;
    float4 bB, cB, x0B, x1B;
    float2 sA, sB;

    SCAN_LOAD(A, 0);
    SCAN_LOAD(B, 1);

    for (int t = 0; t < LL; t += 2) {
        SCAN_STEP(A, t);
        SCAN_STEP(B, t + 1);
    }
}

// ---------------- RMS norm: fused silu(z) gate + rms + permute + tf32 ------
__global__ __launch_bounds__(256) void k_rms(const float* __restrict__ nw) {
    int row = blockIdx.x, j = threadIdx.x;
    size_t rD = (size_t)row * DI;
    const float* zr = g_zx + (size_t)row * PRJ;
    float a0 = g_y[rD + j]       * silu_f(zr[j]);
    float a1 = g_y[rD + 256 + j] * silu_f(zr[256 + j]);
    float v = a0 * a0 + a1 * a1;
    __shared__ float s1[8];
    int lane = j & 31, w = j >> 5;
#pragma unroll
    for (int o = 16; o > 0; o >>= 1) v += __shfl_down_sync(0xffffffffu, v, o);
    if (lane == 0) s1[w] = v;
    __syncthreads();
    if (j == 0) {
        float a = 0.f;
#pragma unroll
        for (int i = 0; i < 8; i++) a += s1[i];
        s1[0] = a * (1.f / DI);
    }
    __syncthreads();
    float sc = rsqrtf(s1[0] + EPSF);
    int pj = permc(j);
    g_y[rD + pj]       = to_tf32(a0 * sc * nw[j]);
    g_y[rD + 256 + pj] = to_tf32(a1 * sc * nw[j + 256]);
}

// ---------------- residual add + layernorm (g_h permuted in/out) ------------
__global__ __launch_bounds__(256) void k_addln(const float* __restrict__ lw,
                                               const float* __restrict__ lb) {
    int row = blockIdx.x, j = threadIdx.x;
    float acc = g_m[(size_t)row * DM + j] + g_h[(size_t)row * DM + permc(j)];
    ln_write256(acc, g_h + (size_t)row * DM, lw, lb, j);
}

// ---------------- masked mean pool (permuted cols, 8 t-slices) --------------
__global__ __launch_bounds__(256) void k_pool(const int* __restrict__ lengths) {
    int b = blockIdx.x, s = blockIdx.y, d = threadIdx.x;
    int len = lengths[b];
    int t0 = s * 128;
    int t1 = min(t0 + 128, len);
    float acc = 0.f;
    const float* base = g_h + ((size_t)b * LL + t0) * DM + d;
#pragma unroll 4
    for (int t = t0; t < t1; t++, base += DM) acc += *base;
    g_poolp[s][b * DM + d] = acc;
}

// ---------------- classification head ---------------------------------------
__global__ __launch_bounds__(NCLS*32) void k_head(const float* __restrict__ hw,
                                                  const float* __restrict__ hb,
                                                  const int* __restrict__ lengths,
                                                  float* __restrict__ out) {
    int b = blockIdx.x;
    int tid = threadIdx.x, c = tid >> 5, lane = tid & 31;
    __shared__ float sp[DM];
    if (tid < DM) {
        float a = 0.f;
#pragma unroll
        for (int s = 0; s < 8; s++) a += g_poolp[s][b * DM + tid];
        sp[permcinv(tid)] = a / (float)lengths[b];
    }
    __syncthreads();
    float acc = 0.f;
    for (int k = lane; k < DM; k += 32) acc += sp[k] * hw[c * DM + k];
#pragma unroll
    for (int o = 16; o > 0; o >>= 1) acc += __shfl_down_sync(0xffffffffu, acc, o);
    if (lane == 0) out[b * NCLS + c] = acc + hb[c];
}

// ---------------- launcher ---------------------------------------------------
extern "C" void kernel_launch(void* const* d_in, const int* in_sizes, int n_in,
                              void* d_out, int out_size) {
    (void)in_sizes; (void)n_in; (void)out_size;
    const float* x        = (const float*)d_in[0];
    const float* in_w     = (const float*)d_in[1];
    const float* in_b     = (const float*)d_in[2];
    const float* lnin_w   = (const float*)d_in[3];
    const float* lnin_b   = (const float*)d_in[4];
    const float* inproj_w = (const float*)d_in[5];
    const float* conv_w   = (const float*)d_in[6];
    const float* conv_b   = (const float*)d_in[7];
    const float* dt_bias  = (const float*)d_in[8];
    const float* A_log    = (const float*)d_in[9];
    const float* Dp       = (const float*)d_in[10];
    const float* norm_w   = (const float*)d_in[11];
    const float* outp_w   = (const float*)d_in[12];
    const float* ln_w     = (const float*)d_in[13];
    const float* ln_b     = (const float*)d_in[14];
    const float* head_w   = (const float*)d_in[15];
    const float* head_b   = (const float*)d_in[16];
    const int*   lengths  = (const int*)d_in[17];
    float* out = (float*)d_out;

    float *ph, *pzx, *py, *pm, *pwin, *pwout;
    cudaGetSymbolAddress((void**)&ph,    g_h);
    cudaGetSymbolAddress((void**)&pzx,   g_zx);
    cudaGetSymbolAddress((void**)&py,    g_y);
    cudaGetSymbolAddress((void**)&pm,    g_m);
    cudaGetSymbolAddress((void**)&pwin,  g_win);
    cudaGetSymbolAddress((void**)&pwout, g_wout);

    cudaFuncSetAttribute(gemm_tf32<true>,  cudaFuncAttributeMaxDynamicSharedMemorySize,
                         GEMM_SMEM);
    cudaFuncSetAttribute(gemm_tf32<false>, cudaFuncAttributeMaxDynamicSharedMemorySize,
                         GEMM_SMEM);

    int totIn  = NLAYER * PRJ * DM;
    int totOut = NLAYER * DM * DI;
    k_permw<<<(totIn  + 255) / 256, 256>>>(inproj_w, pwin,  totIn,  DM - 1);
    k_permw<<<(totOut + 255) / 256, 256>>>(outp_w,   pwout, totOut, DI - 1);

    k_in_ln<<<BLT, 256>>>(x, in_w, in_b, lnin_w, lnin_b);
    for (int i = 0; i < NLAYER; i++) {
        gemm_tf32<true><<<dim3((PRJ + 127) / 128, BLT / 128), 256, GEMM_SMEM>>>(
            ph, pwin + (size_t)i * PRJ * DM, pzx, BLT, PRJ, DM);
        k_conv<<<(BLT * CCH) / 256, 256>>>(conv_w + i * DCV * CCH, conv_b + i * CCH);
        k_dt<<<(BLT * NHH) / 256, 256>>>(dt_bias + i * NHH, A_log + i * NHH);
        k_scan<<<BB * NHH, 256>>>(Dp + i * NHH);
        k_rms<<<BLT, 256>>>(norm_w + i * DI);
        gemm_tf32<false><<<dim3(DM / 128, BLT / 128), 256, GEMM_SMEM>>>(
            py, pwout + (size_t)i * DM * DI, pm, BLT, DM, DI);
        k_addln<<<BLT, 256>>>(ln_w + i * DM, ln_b + i * DM);
    }
    k_pool<<<dim3(BB, 8), 256>>>(lengths);
    k_head<<<BB, NCLS * 32>>>(head_w, head_b, lengths, out);
}

// round 17
// speedup vs baseline: 1.4513x; 1.1997x over previous
#include <cuda_runtime.h>
#include <math.h>

#define BB 32
#define LL 1024
#define BLT (BB*LL)
#define DIN 63
#define DM 256
#define NCLS 14
#define NLAYER 4
#define DI 512
#define DS 128
#define NHH 8
#define HPP 64
#define DCV 4
#define CCH 768
#define PRJ 1288
#define EPSF 1e-5f

// ---------------- scratch (device globals; no cudaMalloc allowed) ----------
__device__ float g_h[BLT*DM];                 // residual (k-permuted cols)
__device__ float g_zx[(size_t)BLT*PRJ];       // inproj output (logical cols)
__device__ float g_xbc[(size_t)BLT*CCH];      // conv+silu output
__device__ float2 g_sc[BLT*NHH];              // packed (dA, dt)
__device__ float g_y[(size_t)BLT*DI];         // scan out (UNGATED) -> rms
__device__ float g_m[BLT*DM];                 // outproj output (logical cols)
__device__ float g_poolp[8][BB*DM];           // partial pools (permuted cols)
__device__ float g_win[(size_t)NLAYER*PRJ*DM];
__device__ float g_wout[(size_t)NLAYER*DM*DI];

// ---------------- column permutation: kp within 32-groups -------------------
__device__ __forceinline__ int permc(int j) {
    return (j & ~31) | (((j & 3) << 3) | ((j & 31) >> 2));
}
__device__ __forceinline__ int permcinv(int j) {
    return (j & ~31) | (((j & 7) << 2) | ((j & 31) >> 3));
}

__device__ __forceinline__ float to_tf32(float x) {
    asm("cvt.rna.tf32.f32 %0, %0;" : "+f"(x));
    return x;
}

// ---------------- fast silu: sigmoid via tanh.approx (1 MUFU) --------------
__device__ __forceinline__ float tanh_ap(float x) {
    float r;
    asm("tanh.approx.f32 %0, %1;" : "=f"(r) : "f"(x));
    return r;
}
__device__ __forceinline__ float silu_f(float x) {
    return x * fmaf(0.5f, tanh_ap(0.5f * x), 0.5f);
}

// ---------------- packed f32x2 helpers --------------------------------------
__device__ __forceinline__ unsigned long long pk2(float lo, float hi) {
    unsigned long long r;
    asm("mov.b64 %0, {%1, %2};" : "=l"(r) : "f"(lo), "f"(hi));
    return r;
}
__device__ __forceinline__ void upk2(float& lo, float& hi, unsigned long long v) {
    asm("mov.b64 {%0, %1}, %2;" : "=f"(lo), "=f"(hi) : "l"(v));
}
__device__ __forceinline__ unsigned long long mul2(unsigned long long a, unsigned long long b) {
    unsigned long long r;
    asm("mul.rn.f32x2 %0, %1, %2;" : "=l"(r) : "l"(a), "l"(b));
    return r;
}
__device__ __forceinline__ unsigned long long fma2(unsigned long long a, unsigned long long b,
                                                   unsigned long long c) {
    unsigned long long r;
    asm("fma.rn.f32x2 %0, %1, %2, %3;" : "=l"(r) : "l"(a), "l"(b), "l"(c));
    return r;
}

// ---------------- cp.async helper -------------------------------------------
__device__ __forceinline__ void cp16(void* dst, const void* src, bool v) {
    unsigned d = (unsigned)__cvta_generic_to_shared(dst);
    int sz = v ? 16 : 0;
    asm volatile("cp.async.ca.shared.global [%0], [%1], 16, %2;"
                 :: "r"(d), "l"(src), "r"(sz) : "memory");
}

// ---------------- weight permute + tf32 round pre-pass ----------------------
__global__ __launch_bounds__(256) void k_permw(const float* __restrict__ W,
                                               float* __restrict__ Wp,
                                               int total, int Kmask) {
    int i = blockIdx.x * 256 + threadIdx.x;
    if (i >= total) return;
    int k = i & Kmask;
    Wp[(i - k) + permc(k)] = to_tf32(W[i]);
}

// ---------------- block layernorm helper (blockDim == 256) -----------------
__device__ __forceinline__ void ln_write256(float acc, float* outp,
                                            const float* __restrict__ w,
                                            const float* __restrict__ b, int j) {
    __shared__ float s1[8], s2[8];
    float v = acc, v2 = acc * acc;
    int lane = j & 31, wp = j >> 5;
#pragma unroll
    for (int o = 16; o > 0; o >>= 1) {
        v  += __shfl_down_sync(0xffffffffu, v,  o);
        v2 += __shfl_down_sync(0xffffffffu, v2, o);
    }
    if (lane == 0) { s1[wp] = v; s2[wp] = v2; }
    __syncthreads();
    if (j == 0) {
        float a = 0.f, c = 0.f;
#pragma unroll
        for (int i = 0; i < 8; i++) { a += s1[i]; c += s2[i]; }
        s1[0] = a * (1.f / DM);
        s2[0] = c * (1.f / DM);
    }
    __syncthreads();
    float mu = s1[0], var = s2[0] - mu * mu;
    outp[permc(j)] = (acc - mu) * rsqrtf(var + EPSF) * w[j] + b[j];
}

// ---------------- input projection + layernorm ------------------------------
__global__ __launch_bounds__(256) void k_in_ln(const float* __restrict__ x,
                                               const float* __restrict__ w,
                                               const float* __restrict__ bias,
                                               const float* __restrict__ gw,
                                               const float* __restrict__ gb) {
    int row = blockIdx.x, j = threadIdx.x;
    __shared__ float sx[DIN];
    if (j < DIN) sx[j] = x[(size_t)row * DIN + j];
    __syncthreads();
    const float* wr = w + j * DIN;
    float acc = bias[j];
#pragma unroll
    for (int k = 0; k < DIN; k++) acc += sx[k] * wr[k];
    ln_write256(acc, g_h + (size_t)row * DM, gw, gb, j);
}

// ================= tf32 tensor-core GEMM (R4 proven version) ===============
__device__ __forceinline__ void mma8(float* c,
                                     unsigned a0, unsigned a1, unsigned a2, unsigned a3,
                                     unsigned b0, unsigned b1) {
    asm volatile(
        "mma.sync.aligned.m16n8k8.row.col.f32.tf32.tf32.f32 "
        "{%0,%1,%2,%3}, {%4,%5,%6,%7}, {%8,%9}, {%0,%1,%2,%3};"
        : "+f"(c[0]), "+f"(c[1]), "+f"(c[2]), "+f"(c[3])
        : "r"(a0), "r"(a1), "r"(a2), "r"(a3), "r"(b0), "r"(b1));
}

#define TPITCH 36
#define GEMM_SMEM (4 * 128 * TPITCH * 4)

template<bool CVTA>
__global__ __launch_bounds__(256, 2) void gemm_tf32(const float* __restrict__ A,
                                                    const float* __restrict__ B,
                                                    float* __restrict__ C,
                                                    int M, int N, int K) {
    extern __shared__ float smem_dyn[];
    float (*As)[128][TPITCH] = (float (*)[128][TPITCH])smem_dyn;
    float (*Bs)[128][TPITCH] = (float (*)[128][TPITCH])(smem_dyn + 2 * 128 * TPITCH);

    int tid = threadIdx.x;
    int bm = blockIdx.y * 128, bn = blockIdx.x * 128;
    int lane = tid & 31, warp = tid >> 5;
    int quad = lane >> 2, tq = lane & 3;
    int wm = (warp & 1) * 64, wn = (warp >> 1) * 32;
    int rr = tid >> 3, cc = tid & 7;

    float acc[4][4][4];
#pragma unroll
    for (int i = 0; i < 4; i++)
#pragma unroll
        for (int j = 0; j < 4; j++)
#pragma unroll
            for (int f = 0; f < 4; f++) acc[i][j][f] = 0.f;

#pragma unroll
    for (int i = 0; i < 4; i++) {
        int r = rr + i * 32;
        cp16(&Bs[0][r][cc * 4], B + (size_t)(bn + r) * K + cc * 4, bn + r < N);
        if (!CVTA)
            cp16(&As[0][r][cc * 4], A + (size_t)(bm + r) * K + cc * 4, true);
    }
    asm volatile("cp.async.commit_group;" ::: "memory");
    if (CVTA) {
#pragma unroll
        for (int i = 0; i < 4; i++) {
            float4 v = *(const float4*)(A + (size_t)(bm + rr + i * 32) * K + cc * 4);
            v.x = to_tf32(v.x); v.y = to_tf32(v.y);
            v.z = to_tf32(v.z); v.w = to_tf32(v.w);
            *(float4*)&As[0][rr + i * 32][cc * 4] = v;
        }
    }

    int nIter = K >> 5;
    for (int it = 0; it < nIter; it++) {
        int cur = it & 1, nb = cur ^ 1;
        bool more = (it + 1 < nIter);

        asm volatile("cp.async.wait_group 0;" ::: "memory");
        __syncthreads();

        if (more) {
            int k0 = (it + 1) << 5;
#pragma unroll
            for (int i = 0; i < 4; i++) {
                int r = rr + i * 32;
                cp16(&Bs[nb][r][cc * 4], B + (size_t)(bn + r) * K + k0 + cc * 4,
                     bn + r < N);
                if (!CVTA)
                    cp16(&As[nb][r][cc * 4], A + (size_t)(bm + r) * K + k0 + cc * 4,
                         true);
            }
            asm volatile("cp.async.commit_group;" ::: "memory");
        }

        __align__(16) unsigned bq[4][8];
#pragma unroll
        for (int j = 0; j < 4; j++) {
            const float* bp = &Bs[cur][wn + j * 8 + quad][tq * 8];
            *(float4*)&bq[j][0] = *(const float4*)bp;
            *(float4*)&bq[j][4] = *(const float4*)(bp + 4);
        }
#pragma unroll
        for (int i = 0; i < 4; i++) {
            __align__(16) unsigned alo[8], ahi[8];
            const float* ap0 = &As[cur][wm + i * 16 + quad][tq * 8];
            const float* ap1 = &As[cur][wm + i * 16 + 8 + quad][tq * 8];
            *(float4*)&alo[0] = *(const float4*)ap0;
            *(float4*)&alo[4] = *(const float4*)(ap0 + 4);
            *(float4*)&ahi[0] = *(const float4*)ap1;
            *(float4*)&ahi[4] = *(const float4*)(ap1 + 4);
#pragma unroll
            for (int j = 0; j < 4; j++)
#pragma unroll
                for (int s = 0; s < 4; s++)
                    mma8(acc[i][j], alo[2 * s], ahi[2 * s], alo[2 * s + 1],
                         ahi[2 * s + 1], bq[j][2 * s], bq[j][2 * s + 1]);
        }

        if (CVTA && more) {
            int k0 = (it + 1) << 5;
#pragma unroll
            for (int i = 0; i < 4; i++) {
                float4 v = *(const float4*)(A + (size_t)(bm + rr + i * 32) * K + k0 + cc * 4);
                v.x = to_tf32(v.x); v.y = to_tf32(v.y);
                v.z = to_tf32(v.z); v.w = to_tf32(v.w);
                *(float4*)&As[nb][rr + i * 32][cc * 4] = v;
            }
        }
    }

#pragma unroll
    for (int i = 0; i < 4; i++) {
        int row = bm + wm + i * 16 + quad;
#pragma unroll
        for (int j = 0; j < 4; j++) {
            int col = bn + wn + j * 8 + tq * 2;
            if (col < N) {
                float2 v0 = make_float2(acc[i][j][0], acc[i][j][1]);
                float2 v1 = make_float2(acc[i][j][2], acc[i][j][3]);
                *(float2*)(C + (size_t)row * N + col) = v0;
                *(float2*)(C + (size_t)(row + 8) * N + col) = v1;
            }
        }
    }
}

// ---------------- causal depthwise conv + silu (tanh-based, 1 MUFU) --------
__global__ __launch_bounds__(256) void k_conv(const float* __restrict__ cw,
                                              const float* __restrict__ cb) {
    int idx = blockIdx.x * 256 + threadIdx.x;
    int c = idx % CCH;
    int row = idx / CCH;
    int t = row & (LL - 1);
    const float* base = g_zx + (size_t)row * PRJ + DI + c;
    float acc = cb[c];
#pragma unroll
    for (int k = 0; k < DCV; k++) {
        int tt = t + k - (DCV - 1);
        if (tt >= 0) acc += base[(long)(k - (DCV - 1)) * PRJ] * cw[k * CCH + c];
    }
    g_xbc[(size_t)row * CCH + c] = silu_f(acc);
}

// ---------------- dt/dA: packed (dA, dt) float2 -----------------------------
__global__ __launch_bounds__(256) void k_dt(const float* __restrict__ dtb,
                                            const float* __restrict__ alog) {
    int idx = blockIdx.x * 256 + threadIdx.x;
    int row = idx >> 3, hh = idx & 7;
    float v = g_zx[(size_t)row * PRJ + DI + CCH + hh] + dtb[hh];
    float dt = (v > 20.f) ? v : log1pf(expf(v));
    float A = -expf(alog[hh]);
    g_sc[idx] = make_float2(expf(dt * A), dt);
}

// ---------------- sequential SSM scan: warp-transposed + tree reduce --------
// one block per (b,h); 256 threads = 8 warps. ng = lane (32 x 4n), pg = warp
// (8 x 8p). Per thread 8p x 4n states. Depth-2 register prefetch.
// Reduction: value-halving exchange tree (9 SHFL vs 40 naive). Lane 4j ends
// holding S_j; writer lanes {0,4,..,28} store 1 float each (1 wavefront).
// Writes UNGATED y + D*x; k_rms applies silu(z).
#define SCAN_LOAD(S, T)                                               \
    do {                                                              \
        const float* r_ = xbase + (size_t)(T) * CCH;                  \
        b##S  = *(const float4*)(r_ + OB);                            \
        c##S  = *(const float4*)(r_ + OC);                            \
        x0##S = *(const float4*)(r_ + OX);                            \
        x1##S = *(const float4*)(r_ + OX + 4);                        \
        xs##S = r_[OX + wsel];                                        \
        s##S  = scbase[(size_t)(T) * NHH];                            \
    } while (0)

#define SCAN_STEP(S, T)                                                     \
    do {                                                                    \
        unsigned long long dA2 = pk2(s##S.x, s##S.x);                       \
        float dtv = s##S.y;                                                 \
        float xa[8] = {x0##S.x, x0##S.y, x0##S.z, x0##S.w,                  \
                       x1##S.x, x1##S.y, x1##S.z, x1##S.w};                 \
        float xw = xs##S;                                                   \
        unsigned long long bp[2], cq[2];                                    \
        bp[0] = pk2(b##S.x, b##S.y); bp[1] = pk2(b##S.z, b##S.w);           \
        cq[0] = pk2(c##S.x, c##S.y); cq[1] = pk2(c##S.z, c##S.w);           \
        if ((T) + 2 < LL) SCAN_LOAD(S, (T) + 2);                            \
        float a8[8];                                                        \
        _Pragma("unroll")                                                   \
        for (int i = 0; i < 8; i++) {                                       \
            float d = dtv * xa[i];                                          \
            unsigned long long dtx = pk2(d, d);                             \
            unsigned long long ap = 0ull;                                   \
            _Pragma("unroll")                                               \
            for (int j = 0; j < 2; j++) {                                   \
                hs[i][j] = fma2(dtx, bp[j], mul2(hs[i][j], dA2));           \
                ap = fma2(hs[i][j], cq[j], ap);                             \
            }                                                               \
            float lo, hi;                                                   \
            upk2(lo, hi, ap);                                               \
            a8[i] = lo + hi;                                                \
        }                                                                   \
        /* tree reduce: 8 values over 32 lanes, 9 SHFL */                   \
        float t4[4], u2[2], sred;                                           \
        _Pragma("unroll")                                                   \
        for (int k = 0; k < 4; k++) {                                       \
            float give = b4sel ? a8[k] : a8[k + 4];                         \
            float got = __shfl_xor_sync(0xffffffffu, give, 16);             \
            t4[k] = (b4sel ? a8[k + 4] : a8[k]) + got;                      \
        }                                                                   \
        _Pragma("unroll")                                                   \
        for (int k = 0; k < 2; k++) {                                       \
            float give = b3sel ? t4[k] : t4[k + 2];                         \
            float got = __shfl_xor_sync(0xffffffffu, give, 8);              \
            u2[k] = (b3sel ? t4[k + 2] : t4[k]) + got;                      \
        }                                                                   \
        {                                                                   \
            float give = b2sel ? u2[0] : u2[1];                             \
            float got = __shfl_xor_sync(0xffffffffu, give, 4);              \
            sred = (b2sel ? u2[1] : u2[0]) + got;                           \
        }                                                                   \
        sred += __shfl_xor_sync(0xffffffffu, sred, 2);                      \
        sred += __shfl_xor_sync(0xffffffffu, sred, 1);                      \
        if (wlo) ybase[(size_t)(T) * DI + wsel] = sred + Dh * xw;           \
    } while (0)

__global__ __launch_bounds__(256, 2) void k_scan(const float* __restrict__ Dp) {
    int bh = blockIdx.x, b = bh >> 3, hh = bh & 7;
    int tid = threadIdx.x;
    int warp = tid >> 5, lane = tid & 31;
    int p0 = warp * 8, n0 = lane * 4;
    bool b4sel = (lane & 16) != 0;
    bool b3sel = (lane & 8) != 0;
    bool b2sel = (lane & 4) != 0;
    int wsel = lane >> 2;                 // value index held by lane 4*wsel
    bool wlo = (lane & 3) == 0;           // writer lanes {0,4,...,28}

    unsigned long long hs[8][2];          // 8p x 4n packed
#pragma unroll
    for (int i = 0; i < 8; i++)
#pragma unroll
        for (int j = 0; j < 2; j++) hs[i][j] = 0ull;

    const float* xbase = g_xbc + (size_t)b * LL * CCH;
    const int OB = DI + n0;
    const int OC = DI + DS + n0;
    const int OX = hh * HPP + p0;
    const float2* scbase = g_sc + (size_t)b * LL * NHH + hh;
    float* ybase = g_y + (size_t)b * LL * DI + hh * HPP + p0;
    float Dh = Dp[hh];

    float4 bA, cA, x0A, x1A;
    float4 bB, cB, x0B, x1B;
    float xsA, xsB;
    float2 sA, sB;

    SCAN_LOAD(A, 0);
    SCAN_LOAD(B, 1);

    for (int t = 0; t < LL; t += 2) {
        SCAN_STEP(A, t);
        SCAN_STEP(B, t + 1);
    }
}

// ---------------- RMS norm: fused silu(z) gate + rms + permute + tf32 ------
__global__ __launch_bounds__(256) void k_rms(const float* __restrict__ nw) {
    int row = blockIdx.x, j = threadIdx.x;
    size_t rD = (size_t)row * DI;
    const float* zr = g_zx + (size_t)row * PRJ;
    float a0 = g_y[rD + j]       * silu_f(zr[j]);
    float a1 = g_y[rD + 256 + j] * silu_f(zr[256 + j]);
    float v = a0 * a0 + a1 * a1;
    __shared__ float s1[8];
    int lane = j & 31, w = j >> 5;
#pragma unroll
    for (int o = 16; o > 0; o >>= 1) v += __shfl_down_sync(0xffffffffu, v, o);
    if (lane == 0) s1[w] = v;
    __syncthreads();
    if (j == 0) {
        float a = 0.f;
#pragma unroll
        for (int i = 0; i < 8; i++) a += s1[i];
        s1[0] = a * (1.f / DI);
    }
    __syncthreads();
    float sc = rsqrtf(s1[0] + EPSF);
    int pj = permc(j);
    g_y[rD + pj]       = to_tf32(a0 * sc * nw[j]);
    g_y[rD + 256 + pj] = to_tf32(a1 * sc * nw[j + 256]);
}

// ---------------- residual add + layernorm (g_h permuted in/out) ------------
__global__ __launch_bounds__(256) void k_addln(const float* __restrict__ lw,
                                               const float* __restrict__ lb) {
    int row = blockIdx.x, j = threadIdx.x;
    float acc = g_m[(size_t)row * DM + j] + g_h[(size_t)row * DM + permc(j)];
    ln_write256(acc, g_h + (size_t)row * DM, lw, lb, j);
}

// ---------------- masked mean pool (permuted cols, 8 t-slices) --------------
__global__ __launch_bounds__(256) void k_pool(const int* __restrict__ lengths) {
    int b = blockIdx.x, s = blockIdx.y, d = threadIdx.x;
    int len = lengths[b];
    int t0 = s * 128;
    int t1 = min(t0 + 128, len);
    float acc = 0.f;
    const float* base = g_h + ((size_t)b * LL + t0) * DM + d;
#pragma unroll 4
    for (int t = t0; t < t1; t++, base += DM) acc += *base;
    g_poolp[s][b * DM + d] = acc;
}

// ---------------- classification head ---------------------------------------
__global__ __launch_bounds__(NCLS*32) void k_head(const float* __restrict__ hw,
                                                  const float* __restrict__ hb,
                                                  const int* __restrict__ lengths,
                                                  float* __restrict__ out) {
    int b = blockIdx.x;
    int tid = threadIdx.x, c = tid >> 5, lane = tid & 31;
    __shared__ float sp[DM];
    if (tid < DM) {
        float a = 0.f;
#pragma unroll
        for (int s = 0; s < 8; s++) a += g_poolp[s][b * DM + tid];
        sp[permcinv(tid)] = a / (float)lengths[b];
    }
    __syncthreads();
    float acc = 0.f;
    for (int k = lane; k < DM; k += 32) acc += sp[k] * hw[c * DM + k];
#pragma unroll
    for (int o = 16; o > 0; o >>= 1) acc += __shfl_down_sync(0xffffffffu, acc, o);
    if (lane == 0) out[b * NCLS + c] = acc + hb[c];
}

// ---------------- launcher ---------------------------------------------------
extern "C" void kernel_launch(void* const* d_in, const int* in_sizes, int n_in,
                              void* d_out, int out_size) {
    (void)in_sizes; (void)n_in; (void)out_size;
    const float* x        = (const float*)d_in[0];
    const float* in_w     = (const float*)d_in[1];
    const float* in_b     = (const float*)d_in[2];
    const float* lnin_w   = (const float*)d_in[3];
    const float* lnin_b   = (const float*)d_in[4];
    const float* inproj_w = (const float*)d_in[5];
    const float* conv_w   = (const float*)d_in[6];
    const float* conv_b   = (const float*)d_in[7];
    const float* dt_bias  = (const float*)d_in[8];
    const float* A_log    = (const float*)d_in[9];
    const float* Dp       = (const float*)d_in[10];
    const float* norm_w   = (const float*)d_in[11];
    const float* outp_w   = (const float*)d_in[12];
    const float* ln_w     = (const float*)d_in[13];
    const float* ln_b     = (const float*)d_in[14];
    const float* head_w   = (const float*)d_in[15];
    const float* head_b   = (const float*)d_in[16];
    const int*   lengths  = (const int*)d_in[17];
    float* out = (float*)d_out;

    float *ph, *pzx, *py, *pm, *pwin, *pwout;
    cudaGetSymbolAddress((void**)&ph,    g_h);
    cudaGetSymbolAddress((void**)&pzx,   g_zx);
    cudaGetSymbolAddress((void**)&py,    g_y);
    cudaGetSymbolAddress((void**)&pm,    g_m);
    cudaGetSymbolAddress((void**)&pwin,  g_win);
    cudaGetSymbolAddress((void**)&pwout, g_wout);

    cudaFuncSetAttribute(gemm_tf32<true>,  cudaFuncAttributeMaxDynamicSharedMemorySize,
                         GEMM_SMEM);
    cudaFuncSetAttribute(gemm_tf32<false>, cudaFuncAttributeMaxDynamicSharedMemorySize,
                         GEMM_SMEM);

    int totIn  = NLAYER * PRJ * DM;
    int totOut = NLAYER * DM * DI;
    k_permw<<<(totIn  + 255) / 256, 256>>>(inproj_w, pwin,  totIn,  DM - 1);
    k_permw<<<(totOut + 255) / 256, 256>>>(outp_w,   pwout, totOut, DI - 1);

    k_in_ln<<<BLT, 256>>>(x, in_w, in_b, lnin_w, lnin_b);
    for (int i = 0; i < NLAYER; i++) {
        gemm_tf32<true><<<dim3((PRJ + 127) / 128, BLT / 128), 256, GEMM_SMEM>>>(
            ph, pwin + (size_t)i * PRJ * DM, pzx, BLT, PRJ, DM);
        k_conv<<<(BLT * CCH) / 256, 256>>>(conv_w + i * DCV * CCH, conv_b + i * CCH);
        k_dt<<<(BLT * NHH) / 256, 256>>>(dt_bias + i * NHH, A_log + i * NHH);
        k_scan<<<BB * NHH, 256>>>(Dp + i * NHH);
        k_rms<<<BLT, 256>>>(norm_w + i * DI);
        gemm_tf32<false><<<dim3(DM / 128, BLT / 128), 256, GEMM_SMEM>>>(
            py, pwout + (size_t)i * DM * DI, pm, BLT, DM, DI);
        k_addln<<<BLT, 256>>>(ln_w + i * DM, ln_b + i * DM);
    }
    k_pool<<<dim3(BB, 8), 256>>>(lengths);
    k_head<<<BB, NCLS * 32>>>(head_w, head_b, lengths, out);
}